// round 8
// baseline (speedup 1.0000x reference)
#include <cuda_runtime.h>
#include <cuda_fp16.h>

#define IN_CH 128
#define HID   64
#define HEADS 4
#define MAXN  50176
#define MAXE  1048576

static __device__ uint4 g_h2[MAXN * 8];       // fp16 projected features [N,64] (128B/node)
static __device__ float g_rn[MAXN * HEADS];   // per-head reciprocal norms [N,4]
static __device__ float g_acc[MAXN * HID];    // aggregated messages [N,64]
static __device__ int   g_cnt[MAXN];          // in-degree per node
static __device__ int   g_start[MAXN];        // CSR start offsets
static __device__ int   g_fill[MAXN];         // scatter cursors
static __device__ int   g_elist[MAXE];        // binned source (col) indices
static __device__ int   g_is64;               // edge_index dtype flag

// ---------------------------------------------------------------------------
// Detect whether edge_index is int64 (high words of in-range values all zero).
// ---------------------------------------------------------------------------
__global__ void detect_dtype_kernel(const int* __restrict__ ei) {
    int cnt = 0;
    for (int i = 0; i < 64; i++) {
        if (ei[2 * i + 1] != 0) cnt++;
    }
    g_is64 = (cnt == 0) ? 1 : 0;
}

// ---------------------------------------------------------------------------
// Kernel 1: h = x @ lin_w^T  (N x 128 @ 128 x 64), fused per-head rnorm,
// fp16 h write, and g_cnt zeroing (for the histogram that follows).
// ---------------------------------------------------------------------------
__global__ void __launch_bounds__(256) gemm_norm_kernel(
    const float* __restrict__ x, const float* __restrict__ w, int N)
{
    __shared__ float xs[32][68];  // xs[k][m]
    __shared__ float ws[32][68];  // ws[k][j]

    const int tid = threadIdx.x;
    const int tx = tid & 15;
    const int ty = tid >> 4;
    const int nb = blockIdx.x * 64;

    float acc[4][4];
#pragma unroll
    for (int a = 0; a < 4; a++)
#pragma unroll
        for (int b = 0; b < 4; b++) acc[a][b] = 0.f;

    for (int kc = 0; kc < IN_CH; kc += 32) {
#pragma unroll
        for (int r = 0; r < 2; r++) {
            int idx = tid + 256 * r;
            int m = idx & 63, k4 = idx >> 6;
            float4 v = make_float4(0.f, 0.f, 0.f, 0.f);
            int node = nb + m;
            if (node < N)
                v = *reinterpret_cast<const float4*>(&x[node * IN_CH + kc + k4 * 4]);
            xs[k4 * 4 + 0][m] = v.x; xs[k4 * 4 + 1][m] = v.y;
            xs[k4 * 4 + 2][m] = v.z; xs[k4 * 4 + 3][m] = v.w;
        }
#pragma unroll
        for (int r = 0; r < 2; r++) {
            int idx = tid + 256 * r;
            int j = idx & 63, k4 = idx >> 6;
            float4 v = *reinterpret_cast<const float4*>(&w[j * IN_CH + kc + k4 * 4]);
            ws[k4 * 4 + 0][j] = v.x; ws[k4 * 4 + 1][j] = v.y;
            ws[k4 * 4 + 2][j] = v.z; ws[k4 * 4 + 3][j] = v.w;
        }
        __syncthreads();

#pragma unroll
        for (int k = 0; k < 32; k++) {
            float4 xv = *reinterpret_cast<float4*>(&xs[k][ty * 4]);
            float4 wv = *reinterpret_cast<float4*>(&ws[k][tx * 4]);
            float xr[4] = {xv.x, xv.y, xv.z, xv.w};
            float wr[4] = {wv.x, wv.y, wv.z, wv.w};
#pragma unroll
            for (int a = 0; a < 4; a++)
#pragma unroll
                for (int b = 0; b < 4; b++) acc[a][b] += xr[a] * wr[b];
        }
        __syncthreads();
    }

#pragma unroll
    for (int mi = 0; mi < 4; mi++) {
        int node = nb + ty * 4 + mi;
        float s = acc[mi][0] * acc[mi][0] + acc[mi][1] * acc[mi][1]
                + acc[mi][2] * acc[mi][2] + acc[mi][3] * acc[mi][3];
        s += __shfl_xor_sync(0xffffffffu, s, 1);
        s += __shfl_xor_sync(0xffffffffu, s, 2);
        if (node < N) {
            __half2* hp = reinterpret_cast<__half2*>(g_h2) + node * 32 + tx * 2;
            hp[0] = __floats2half2_rn(acc[mi][0], acc[mi][1]);
            hp[1] = __floats2half2_rn(acc[mi][2], acc[mi][3]);
            if (tx == 0) g_cnt[node] = 0;
            if ((tx & 3) == 0) {
                g_rn[node * HEADS + (tx >> 2)] = 1.0f / fmaxf(sqrtf(s), 1e-12f);
            }
        }
    }
}

// ---------------------------------------------------------------------------
// Kernel 2a: in-degree histogram.
// ---------------------------------------------------------------------------
__global__ void __launch_bounds__(256) hist_kernel(
    const long long* __restrict__ ei, int E)
{
    int e = blockIdx.x * 256 + threadIdx.x;
    if (e >= E) return;
    int row = g_is64 ? (int)ei[e] : reinterpret_cast<const int*>(ei)[e];
    atomicAdd(&g_cnt[row], 1);
}

// ---------------------------------------------------------------------------
// Kernel 2b: exclusive prefix scan over g_cnt (single block, 1024 threads).
// ---------------------------------------------------------------------------
__global__ void __launch_bounds__(1024) scan_kernel(int N)
{
    __shared__ int sb[1024];
    const int t = threadIdx.x;
    const int C = (N + 1023) >> 10;
    const int base = t * C;

    int s = 0;
    for (int i = 0; i < C; i++) {
        int idx = base + i;
        if (idx < N) s += g_cnt[idx];
    }
    sb[t] = s;
    __syncthreads();
    int mine = s;
    for (int off = 1; off < 1024; off <<= 1) {
        int v = (t >= off) ? sb[t - off] : 0;
        __syncthreads();
        sb[t] += v;
        __syncthreads();
    }
    int run = sb[t] - mine;   // exclusive prefix of this thread's chunk
    for (int i = 0; i < C; i++) {
        int idx = base + i;
        if (idx < N) {
            g_start[idx] = run;
            g_fill[idx] = run;
            run += g_cnt[idx];
        }
    }
}

// ---------------------------------------------------------------------------
// Kernel 2c: scatter source (col) indices into per-row bins.
// ---------------------------------------------------------------------------
__global__ void __launch_bounds__(256) scatter_kernel(
    const long long* __restrict__ ei, int E)
{
    int e = blockIdx.x * 256 + threadIdx.x;
    if (e >= E) return;
    int row, col;
    if (g_is64) {
        row = (int)ei[e];
        col = (int)ei[E + e];
    } else {
        const int* p = reinterpret_cast<const int*>(ei);
        row = p[e];
        col = p[E + e];
    }
    int pos = atomicAdd(&g_fill[row], 1);
    g_elist[pos] = col;
}

// ---------------------------------------------------------------------------
// Kernel 2d: atomic-free aggregation. One warp per target node.
// Lane layout: 8 edge groups (g = lane>>2) x 4 head slices (t = lane&3).
// Lane t owns the FULL head t (dims 16t..16t+15, two uint4 loads), so the
// head dot product is lane-local: NO shuffles inside the divergent loop
// (the R7 bug was a full-mask shfl in a loop with group-dependent trip
// counts -- UB). Cross-group reduction happens after the loop at full
// warp convergence.
// ---------------------------------------------------------------------------
__global__ void __launch_bounds__(256) accum_kernel(int N)
{
    const int warp = (blockIdx.x * 256 + threadIdx.x) >> 5;
    const int lane = threadIdx.x & 31;
    if (warp >= N) return;
    const int n = warp;
    const int g = lane >> 2;     // edge group 0..7
    const int t = lane & 3;      // head index 0..3

    // Row features for head t: dims 16t..16t+15.
    uint4 rv0 = g_h2[n * 8 + 2 * t];
    uint4 rv1 = g_h2[n * 8 + 2 * t + 1];
    float2 r[8];
    {
        const __half2* rh0 = reinterpret_cast<const __half2*>(&rv0);
        const __half2* rh1 = reinterpret_cast<const __half2*>(&rv1);
#pragma unroll
        for (int i = 0; i < 4; i++) { r[i] = __half22float2(rh0[i]); r[i + 4] = __half22float2(rh1[i]); }
    }
    const float rnr = g_rn[n * HEADS + t];

    const int start = g_start[n];
    const int cnt = g_cnt[n];

    float acc[16];
#pragma unroll
    for (int i = 0; i < 16; i++) acc[i] = 0.f;

    for (int i = g; i < cnt; i += 8) {
        int col = g_elist[start + i];
        uint4 cv0 = g_h2[col * 8 + 2 * t];
        uint4 cv1 = g_h2[col * 8 + 2 * t + 1];
        const __half2* ch0 = reinterpret_cast<const __half2*>(&cv0);
        const __half2* ch1 = reinterpret_cast<const __half2*>(&cv1);
        float2 c[8];
#pragma unroll
        for (int j = 0; j < 4; j++) { c[j] = __half22float2(ch0[j]); c[j + 4] = __half22float2(ch1[j]); }

        float d = 0.f;
#pragma unroll
        for (int j = 0; j < 8; j++) d += c[j].x * r[j].x + c[j].y * r[j].y;

        float cosv = d * g_rn[col * HEADS + t] * rnr;
        cosv = fminf(fmaxf(cosv, 1e-6f), 1.0f);    // clip; B_EXP=2 => scale=cos

#pragma unroll
        for (int j = 0; j < 8; j++) {
            acc[2 * j + 0] += c[j].x * cosv;
            acc[2 * j + 1] += c[j].y * cosv;
        }
    }

    // Reduce across the 8 edge groups (lane bits 2..4), fully converged here.
#pragma unroll
    for (int j = 0; j < 16; j++) {
        acc[j] += __shfl_xor_sync(0xffffffffu, acc[j], 4);
        acc[j] += __shfl_xor_sync(0xffffffffu, acc[j], 8);
        acc[j] += __shfl_xor_sync(0xffffffffu, acc[j], 16);
    }

    if (g == 0) {
        float* p = &g_acc[n * HID + t * 16];
        *reinterpret_cast<float4*>(p +  0) = make_float4(acc[0],  acc[1],  acc[2],  acc[3]);
        *reinterpret_cast<float4*>(p +  4) = make_float4(acc[4],  acc[5],  acc[6],  acc[7]);
        *reinterpret_cast<float4*>(p +  8) = make_float4(acc[8],  acc[9],  acc[10], acc[11]);
        *reinterpret_cast<float4*>(p + 12) = make_float4(acc[12], acc[13], acc[14], acc[15]);
    }
}

// ---------------------------------------------------------------------------
// Kernel 3: BcosLinearNoBias (64x64 GEMM) + LayerNorm, persistent blocks.
// ---------------------------------------------------------------------------
__global__ void __launch_bounds__(256) final_kernel(
    const float* __restrict__ bw, const float* __restrict__ gamma,
    const float* __restrict__ beta, float* __restrict__ out, int N)
{
    __shared__ float as[64][68];    // as[k][m]   acc tile (transposed)
    __shared__ float ws[64][68];    // ws[k][j]   bw tile (transposed)
    __shared__ float psum[4][64];   // per-quarter partial row sumsq
    __shared__ float orn_s[64];     // 1/||acc_row||
    __shared__ float wrn_s[64];     // 1/||bw_j||

    const int tid = threadIdx.x;
    const int tx = tid & 15;
    const int ty = tid >> 4;

    {
        const int j = tid & 63;
        const int q = tid >> 6;
#pragma unroll
        for (int rr = 0; rr < 4; rr++) {
            int k4 = q + 4 * rr;
            float4 v = *reinterpret_cast<const float4*>(&bw[j * HID + k4 * 4]);
            ws[k4 * 4 + 0][j] = v.x; ws[k4 * 4 + 1][j] = v.y;
            ws[k4 * 4 + 2][j] = v.z; ws[k4 * 4 + 3][j] = v.w;
        }
    }
    __syncthreads();
    if (tid < 64) {
        float s = 0.f;
#pragma unroll
        for (int k = 0; k < 64; k++) { float v = ws[k][tid]; s += v * v; }
        wrn_s[tid] = 1.0f / fmaxf(sqrtf(s), 1e-12f);
    }
    __syncthreads();

    const float w0 = wrn_s[tx * 4 + 0], w1 = wrn_s[tx * 4 + 1];
    const float w2 = wrn_s[tx * 4 + 2], w3 = wrn_s[tx * 4 + 3];
    const float4 gm = *reinterpret_cast<const float4*>(&gamma[tx * 4]);
    const float4 bt = *reinterpret_cast<const float4*>(&beta[tx * 4]);

    const int ntiles = (N + 63) >> 6;
    for (int tile = blockIdx.x; tile < ntiles; tile += gridDim.x) {
        const int nb = tile * 64;

        {
            const int m = tid & 63;
            const int q = tid >> 6;
            const int node = nb + m;
            float ss = 0.f;
#pragma unroll
            for (int rr = 0; rr < 4; rr++) {
                int k4 = q + 4 * rr;
                float4 v = make_float4(0.f, 0.f, 0.f, 0.f);
                if (node < N)
                    v = *reinterpret_cast<const float4*>(&g_acc[node * HID + k4 * 4]);
                as[k4 * 4 + 0][m] = v.x; as[k4 * 4 + 1][m] = v.y;
                as[k4 * 4 + 2][m] = v.z; as[k4 * 4 + 3][m] = v.w;
                ss += v.x * v.x + v.y * v.y + v.z * v.z + v.w * v.w;
            }
            psum[q][m] = ss;
        }
        __syncthreads();

        if (tid < 64) {
            float s = psum[0][tid] + psum[1][tid] + psum[2][tid] + psum[3][tid];
            orn_s[tid] = 1.0f / fmaxf(sqrtf(s), 1e-12f);
        }

        float acc[4][4];
#pragma unroll
        for (int a = 0; a < 4; a++)
#pragma unroll
            for (int b = 0; b < 4; b++) acc[a][b] = 0.f;

#pragma unroll
        for (int k = 0; k < 64; k++) {
            float4 xv = *reinterpret_cast<float4*>(&as[k][ty * 4]);
            float4 wv = *reinterpret_cast<float4*>(&ws[k][tx * 4]);
            float xr[4] = {xv.x, xv.y, xv.z, xv.w};
            float wr[4] = {wv.x, wv.y, wv.z, wv.w};
#pragma unroll
            for (int a = 0; a < 4; a++)
#pragma unroll
                for (int b = 0; b < 4; b++) acc[a][b] += xr[a] * wr[b];
        }
        __syncthreads();

#pragma unroll
        for (int mi = 0; mi < 4; mi++) {
            const int node = nb + ty * 4 + mi;
            const float orn = orn_s[ty * 4 + mi];

            float l0 = acc[mi][0], l1 = acc[mi][1], l2 = acc[mi][2], l3 = acc[mi][3];
            float y0 = l0 * fminf(fmaxf(l0 * orn * w0, 1e-6f), 1.0f);
            float y1 = l1 * fminf(fmaxf(l1 * orn * w1, 1e-6f), 1.0f);
            float y2 = l2 * fminf(fmaxf(l2 * orn * w2, 1e-6f), 1.0f);
            float y3 = l3 * fminf(fmaxf(l3 * orn * w3, 1e-6f), 1.0f);

            float sum = y0 + y1 + y2 + y3;
#pragma unroll
            for (int o = 8; o > 0; o >>= 1) sum += __shfl_xor_sync(0xffffffffu, sum, o);
            float mu = sum * (1.0f / 64.0f);

            float d0 = y0 - mu, d1 = y1 - mu, d2 = y2 - mu, d3 = y3 - mu;
            float vs = d0 * d0 + d1 * d1 + d2 * d2 + d3 * d3;
#pragma unroll
            for (int o = 8; o > 0; o >>= 1) vs += __shfl_xor_sync(0xffffffffu, vs, o);
            float inv = rsqrtf(vs * (1.0f / 64.0f) + 1e-5f);

            if (node < N) {
                float4 ov = make_float4(d0 * inv * gm.x + bt.x,
                                        d1 * inv * gm.y + bt.y,
                                        d2 * inv * gm.z + bt.z,
                                        d3 * inv * gm.w + bt.w);
                *reinterpret_cast<float4*>(&out[node * HID + tx * 4]) = ov;
            }
        }
        __syncthreads();
    }
}

// ---------------------------------------------------------------------------
extern "C" void kernel_launch(void* const* d_in, const int* in_sizes, int n_in,
                              void* d_out, int out_size)
{
    const float*     x     = (const float*)d_in[0];
    const long long* ei    = (const long long*)d_in[1];
    const float*     lin_w = (const float*)d_in[2];
    const float*     bw    = (const float*)d_in[3];
    const float*     gamma = (const float*)d_in[4];
    const float*     beta  = (const float*)d_in[5];

    const int N = in_sizes[0] / IN_CH;
    const int E = in_sizes[1] / 2;

    detect_dtype_kernel<<<1, 1>>>((const int*)ei);
    gemm_norm_kernel<<<(N + 63) / 64, 256>>>(x, lin_w, N);
    hist_kernel<<<(E + 255) / 256, 256>>>(ei, E);
    scan_kernel<<<1, 1024>>>(N);
    scatter_kernel<<<(E + 255) / 256, 256>>>(ei, E);
    accum_kernel<<<(N + 7) / 8, 256>>>(N);
    final_kernel<<<296, 256>>>(bw, gamma, beta, (float*)d_out, N);
}

// round 9
// speedup vs baseline: 1.6552x; 1.6552x over previous
#include <cuda_runtime.h>
#include <cuda_fp16.h>

#define IN_CH 128
#define HID   64
#define HEADS 4
#define MAXN  50176
#define MAXE  1048576

static __device__ uint4 g_h2[MAXN * 8];       // fp16 projected features [N,64] (128B/node)
static __device__ float g_rn[MAXN * HEADS];   // per-head reciprocal norms [N,4]
static __device__ float g_acc[MAXN * HID];    // aggregated messages [N,64]
static __device__ int   g_cnt[MAXN];          // in-degree per node
static __device__ int   g_start[MAXN];        // bin start offsets
static __device__ int   g_fill[MAXN];         // scatter cursors
static __device__ int   g_elist[MAXE];        // binned source (col) indices
static __device__ int   g_total;              // global bin cursor
static __device__ int   g_is64;               // edge_index dtype flag

// ---------------------------------------------------------------------------
// Detect edge_index dtype; also reset the global bin cursor for this replay.
// ---------------------------------------------------------------------------
__global__ void detect_dtype_kernel(const int* __restrict__ ei) {
    int cnt = 0;
    for (int i = 0; i < 64; i++) {
        if (ei[2 * i + 1] != 0) cnt++;
    }
    g_is64 = (cnt == 0) ? 1 : 0;
    g_total = 0;
}

// ---------------------------------------------------------------------------
// Kernel 1: h = x @ lin_w^T  (N x 128 @ 128 x 64), fused per-head rnorm,
// fp16 h write, and g_cnt zeroing (for the histogram that follows).
// ---------------------------------------------------------------------------
__global__ void __launch_bounds__(256) gemm_norm_kernel(
    const float* __restrict__ x, const float* __restrict__ w, int N)
{
    __shared__ float xs[32][68];  // xs[k][m]
    __shared__ float ws[32][68];  // ws[k][j]

    const int tid = threadIdx.x;
    const int tx = tid & 15;
    const int ty = tid >> 4;
    const int nb = blockIdx.x * 64;

    float acc[4][4];
#pragma unroll
    for (int a = 0; a < 4; a++)
#pragma unroll
        for (int b = 0; b < 4; b++) acc[a][b] = 0.f;

    for (int kc = 0; kc < IN_CH; kc += 32) {
#pragma unroll
        for (int r = 0; r < 2; r++) {
            int idx = tid + 256 * r;
            int m = idx & 63, k4 = idx >> 6;
            float4 v = make_float4(0.f, 0.f, 0.f, 0.f);
            int node = nb + m;
            if (node < N)
                v = *reinterpret_cast<const float4*>(&x[node * IN_CH + kc + k4 * 4]);
            xs[k4 * 4 + 0][m] = v.x; xs[k4 * 4 + 1][m] = v.y;
            xs[k4 * 4 + 2][m] = v.z; xs[k4 * 4 + 3][m] = v.w;
        }
#pragma unroll
        for (int r = 0; r < 2; r++) {
            int idx = tid + 256 * r;
            int j = idx & 63, k4 = idx >> 6;
            float4 v = *reinterpret_cast<const float4*>(&w[j * IN_CH + kc + k4 * 4]);
            ws[k4 * 4 + 0][j] = v.x; ws[k4 * 4 + 1][j] = v.y;
            ws[k4 * 4 + 2][j] = v.z; ws[k4 * 4 + 3][j] = v.w;
        }
        __syncthreads();

#pragma unroll
        for (int k = 0; k < 32; k++) {
            float4 xv = *reinterpret_cast<float4*>(&xs[k][ty * 4]);
            float4 wv = *reinterpret_cast<float4*>(&ws[k][tx * 4]);
            float xr[4] = {xv.x, xv.y, xv.z, xv.w};
            float wr[4] = {wv.x, wv.y, wv.z, wv.w};
#pragma unroll
            for (int a = 0; a < 4; a++)
#pragma unroll
                for (int b = 0; b < 4; b++) acc[a][b] += xr[a] * wr[b];
        }
        __syncthreads();
    }

#pragma unroll
    for (int mi = 0; mi < 4; mi++) {
        int node = nb + ty * 4 + mi;
        float s = acc[mi][0] * acc[mi][0] + acc[mi][1] * acc[mi][1]
                + acc[mi][2] * acc[mi][2] + acc[mi][3] * acc[mi][3];
        s += __shfl_xor_sync(0xffffffffu, s, 1);
        s += __shfl_xor_sync(0xffffffffu, s, 2);
        if (node < N) {
            __half2* hp = reinterpret_cast<__half2*>(g_h2) + node * 32 + tx * 2;
            hp[0] = __floats2half2_rn(acc[mi][0], acc[mi][1]);
            hp[1] = __floats2half2_rn(acc[mi][2], acc[mi][3]);
            if (tx == 0) g_cnt[node] = 0;
            if ((tx & 3) == 0) {
                g_rn[node * HEADS + (tx >> 2)] = 1.0f / fmaxf(sqrtf(s), 1e-12f);
            }
        }
    }
}

// ---------------------------------------------------------------------------
// Kernel 2a: in-degree histogram.
// ---------------------------------------------------------------------------
__global__ void __launch_bounds__(256) hist_kernel(
    const long long* __restrict__ ei, int E)
{
    int e = blockIdx.x * 256 + threadIdx.x;
    if (e >= E) return;
    int row = g_is64 ? (int)ei[e] : reinterpret_cast<const int*>(ei)[e];
    atomicAdd(&g_cnt[row], 1);
}

// ---------------------------------------------------------------------------
// Kernel 2b: bin offset assignment. Bins need only be DISJOINT, not ordered,
// so instead of a global prefix scan (R8's 82us single-block serial scan),
// each warp scans its 32 counts with shuffles and lane 31 grabs a base from
// a single global cursor (1563 atomics total).
// ---------------------------------------------------------------------------
__global__ void __launch_bounds__(256) offsets_kernel(int N)
{
    const int idx = blockIdx.x * 256 + threadIdx.x;
    const int lane = threadIdx.x & 31;
    const int cnt = (idx < N) ? g_cnt[idx] : 0;

    // Inclusive warp scan.
    int incl = cnt;
#pragma unroll
    for (int off = 1; off < 32; off <<= 1) {
        int v = __shfl_up_sync(0xffffffffu, incl, off);
        if (lane >= off) incl += v;
    }
    int base = 0;
    if (lane == 31) base = atomicAdd(&g_total, incl);
    base = __shfl_sync(0xffffffffu, base, 31);

    if (idx < N) {
        int s = base + incl - cnt;
        g_start[idx] = s;
        g_fill[idx] = s;
    }
}

// ---------------------------------------------------------------------------
// Kernel 2c: scatter source (col) indices into per-row bins.
// ---------------------------------------------------------------------------
__global__ void __launch_bounds__(256) scatter_kernel(
    const long long* __restrict__ ei, int E)
{
    int e = blockIdx.x * 256 + threadIdx.x;
    if (e >= E) return;
    int row, col;
    if (g_is64) {
        row = (int)ei[e];
        col = (int)ei[E + e];
    } else {
        const int* p = reinterpret_cast<const int*>(ei);
        row = p[e];
        col = p[E + e];
    }
    int pos = atomicAdd(&g_fill[row], 1);
    g_elist[pos] = col;
}

// ---------------------------------------------------------------------------
// Kernel 2d: atomic-free aggregation. One warp per target node.
// Lane layout: 8 edge groups (g = lane>>2) x 4 head slices (t = lane&3).
// Lane t owns the FULL head t (dims 16t..16t+15): head dot is lane-local,
// so the divergent loop contains no shuffles. Cross-group reduction after
// the loop at full warp convergence.
// ---------------------------------------------------------------------------
__global__ void __launch_bounds__(256) accum_kernel(int N)
{
    const int warp = (blockIdx.x * 256 + threadIdx.x) >> 5;
    const int lane = threadIdx.x & 31;
    if (warp >= N) return;
    const int n = warp;
    const int g = lane >> 2;     // edge group 0..7
    const int t = lane & 3;      // head index 0..3

    uint4 rv0 = g_h2[n * 8 + 2 * t];
    uint4 rv1 = g_h2[n * 8 + 2 * t + 1];
    float2 r[8];
    {
        const __half2* rh0 = reinterpret_cast<const __half2*>(&rv0);
        const __half2* rh1 = reinterpret_cast<const __half2*>(&rv1);
#pragma unroll
        for (int i = 0; i < 4; i++) { r[i] = __half22float2(rh0[i]); r[i + 4] = __half22float2(rh1[i]); }
    }
    const float rnr = g_rn[n * HEADS + t];

    const int start = g_start[n];
    const int cnt = g_cnt[n];

    float acc[16];
#pragma unroll
    for (int i = 0; i < 16; i++) acc[i] = 0.f;

    for (int i = g; i < cnt; i += 8) {
        int col = g_elist[start + i];
        uint4 cv0 = g_h2[col * 8 + 2 * t];
        uint4 cv1 = g_h2[col * 8 + 2 * t + 1];
        const __half2* ch0 = reinterpret_cast<const __half2*>(&cv0);
        const __half2* ch1 = reinterpret_cast<const __half2*>(&cv1);
        float2 c[8];
#pragma unroll
        for (int j = 0; j < 4; j++) { c[j] = __half22float2(ch0[j]); c[j + 4] = __half22float2(ch1[j]); }

        float d = 0.f;
#pragma unroll
        for (int j = 0; j < 8; j++) d += c[j].x * r[j].x + c[j].y * r[j].y;

        float cosv = d * g_rn[col * HEADS + t] * rnr;
        cosv = fminf(fmaxf(cosv, 1e-6f), 1.0f);    // clip; B_EXP=2 => scale=cos

#pragma unroll
        for (int j = 0; j < 8; j++) {
            acc[2 * j + 0] += c[j].x * cosv;
            acc[2 * j + 1] += c[j].y * cosv;
        }
    }

#pragma unroll
    for (int j = 0; j < 16; j++) {
        acc[j] += __shfl_xor_sync(0xffffffffu, acc[j], 4);
        acc[j] += __shfl_xor_sync(0xffffffffu, acc[j], 8);
        acc[j] += __shfl_xor_sync(0xffffffffu, acc[j], 16);
    }

    if (g == 0) {
        float* p = &g_acc[n * HID + t * 16];
        *reinterpret_cast<float4*>(p +  0) = make_float4(acc[0],  acc[1],  acc[2],  acc[3]);
        *reinterpret_cast<float4*>(p +  4) = make_float4(acc[4],  acc[5],  acc[6],  acc[7]);
        *reinterpret_cast<float4*>(p +  8) = make_float4(acc[8],  acc[9],  acc[10], acc[11]);
        *reinterpret_cast<float4*>(p + 12) = make_float4(acc[12], acc[13], acc[14], acc[15]);
    }
}

// ---------------------------------------------------------------------------
// Kernel 3: BcosLinearNoBias (64x64 GEMM) + LayerNorm, persistent blocks.
// ---------------------------------------------------------------------------
__global__ void __launch_bounds__(256) final_kernel(
    const float* __restrict__ bw, const float* __restrict__ gamma,
    const float* __restrict__ beta, float* __restrict__ out, int N)
{
    __shared__ float as[64][68];    // as[k][m]   acc tile (transposed)
    __shared__ float ws[64][68];    // ws[k][j]   bw tile (transposed)
    __shared__ float psum[4][64];   // per-quarter partial row sumsq
    __shared__ float orn_s[64];     // 1/||acc_row||
    __shared__ float wrn_s[64];     // 1/||bw_j||

    const int tid = threadIdx.x;
    const int tx = tid & 15;
    const int ty = tid >> 4;

    {
        const int j = tid & 63;
        const int q = tid >> 6;
#pragma unroll
        for (int rr = 0; rr < 4; rr++) {
            int k4 = q + 4 * rr;
            float4 v = *reinterpret_cast<const float4*>(&bw[j * HID + k4 * 4]);
            ws[k4 * 4 + 0][j] = v.x; ws[k4 * 4 + 1][j] = v.y;
            ws[k4 * 4 + 2][j] = v.z; ws[k4 * 4 + 3][j] = v.w;
        }
    }
    __syncthreads();
    if (tid < 64) {
        float s = 0.f;
#pragma unroll
        for (int k = 0; k < 64; k++) { float v = ws[k][tid]; s += v * v; }
        wrn_s[tid] = 1.0f / fmaxf(sqrtf(s), 1e-12f);
    }
    __syncthreads();

    const float w0 = wrn_s[tx * 4 + 0], w1 = wrn_s[tx * 4 + 1];
    const float w2 = wrn_s[tx * 4 + 2], w3 = wrn_s[tx * 4 + 3];
    const float4 gm = *reinterpret_cast<const float4*>(&gamma[tx * 4]);
    const float4 bt = *reinterpret_cast<const float4*>(&beta[tx * 4]);

    const int ntiles = (N + 63) >> 6;
    for (int tile = blockIdx.x; tile < ntiles; tile += gridDim.x) {
        const int nb = tile * 64;

        {
            const int m = tid & 63;
            const int q = tid >> 6;
            const int node = nb + m;
            float ss = 0.f;
#pragma unroll
            for (int rr = 0; rr < 4; rr++) {
                int k4 = q + 4 * rr;
                float4 v = make_float4(0.f, 0.f, 0.f, 0.f);
                if (node < N)
                    v = *reinterpret_cast<const float4*>(&g_acc[node * HID + k4 * 4]);
                as[k4 * 4 + 0][m] = v.x; as[k4 * 4 + 1][m] = v.y;
                as[k4 * 4 + 2][m] = v.z; as[k4 * 4 + 3][m] = v.w;
                ss += v.x * v.x + v.y * v.y + v.z * v.z + v.w * v.w;
            }
            psum[q][m] = ss;
        }
        __syncthreads();

        if (tid < 64) {
            float s = psum[0][tid] + psum[1][tid] + psum[2][tid] + psum[3][tid];
            orn_s[tid] = 1.0f / fmaxf(sqrtf(s), 1e-12f);
        }

        float acc[4][4];
#pragma unroll
        for (int a = 0; a < 4; a++)
#pragma unroll
            for (int b = 0; b < 4; b++) acc[a][b] = 0.f;

#pragma unroll
        for (int k = 0; k < 64; k++) {
            float4 xv = *reinterpret_cast<float4*>(&as[k][ty * 4]);
            float4 wv = *reinterpret_cast<float4*>(&ws[k][tx * 4]);
            float xr[4] = {xv.x, xv.y, xv.z, xv.w};
            float wr[4] = {wv.x, wv.y, wv.z, wv.w};
#pragma unroll
            for (int a = 0; a < 4; a++)
#pragma unroll
                for (int b = 0; b < 4; b++) acc[a][b] += xr[a] * wr[b];
        }
        __syncthreads();

#pragma unroll
        for (int mi = 0; mi < 4; mi++) {
            const int node = nb + ty * 4 + mi;
            const float orn = orn_s[ty * 4 + mi];

            float l0 = acc[mi][0], l1 = acc[mi][1], l2 = acc[mi][2], l3 = acc[mi][3];
            float y0 = l0 * fminf(fmaxf(l0 * orn * w0, 1e-6f), 1.0f);
            float y1 = l1 * fminf(fmaxf(l1 * orn * w1, 1e-6f), 1.0f);
            float y2 = l2 * fminf(fmaxf(l2 * orn * w2, 1e-6f), 1.0f);
            float y3 = l3 * fminf(fmaxf(l3 * orn * w3, 1e-6f), 1.0f);

            float sum = y0 + y1 + y2 + y3;
#pragma unroll
            for (int o = 8; o > 0; o >>= 1) sum += __shfl_xor_sync(0xffffffffu, sum, o);
            float mu = sum * (1.0f / 64.0f);

            float d0 = y0 - mu, d1 = y1 - mu, d2 = y2 - mu, d3 = y3 - mu;
            float vs = d0 * d0 + d1 * d1 + d2 * d2 + d3 * d3;
#pragma unroll
            for (int o = 8; o > 0; o >>= 1) vs += __shfl_xor_sync(0xffffffffu, vs, o);
            float inv = rsqrtf(vs * (1.0f / 64.0f) + 1e-5f);

            if (node < N) {
                float4 ov = make_float4(d0 * inv * gm.x + bt.x,
                                        d1 * inv * gm.y + bt.y,
                                        d2 * inv * gm.z + bt.z,
                                        d3 * inv * gm.w + bt.w);
                *reinterpret_cast<float4*>(&out[node * HID + tx * 4]) = ov;
            }
        }
        __syncthreads();
    }
}

// ---------------------------------------------------------------------------
extern "C" void kernel_launch(void* const* d_in, const int* in_sizes, int n_in,
                              void* d_out, int out_size)
{
    const float*     x     = (const float*)d_in[0];
    const long long* ei    = (const long long*)d_in[1];
    const float*     lin_w = (const float*)d_in[2];
    const float*     bw    = (const float*)d_in[3];
    const float*     gamma = (const float*)d_in[4];
    const float*     beta  = (const float*)d_in[5];

    const int N = in_sizes[0] / IN_CH;
    const int E = in_sizes[1] / 2;

    detect_dtype_kernel<<<1, 1>>>((const int*)ei);
    gemm_norm_kernel<<<(N + 63) / 64, 256>>>(x, lin_w, N);
    hist_kernel<<<(E + 255) / 256, 256>>>(ei, E);
    offsets_kernel<<<(N + 255) / 256, 256>>>(N);
    scatter_kernel<<<(E + 255) / 256, 256>>>(ei, E);
    accum_kernel<<<(N + 7) / 8, 256>>>(N);
    final_kernel<<<296, 256>>>(bw, gamma, beta, (float*)d_out, N);
}

// round 10
// speedup vs baseline: 2.0151x; 1.2174x over previous
#include <cuda_runtime.h>
#include <cuda_fp16.h>

#define IN_CH 128
#define HID   64
#define HEADS 4
#define MAXN  50176
#define MAXE  1048576

static __device__ uint4 g_h2[MAXN * 8];       // fp16 projected features [N,64] (128B/node)
static __device__ float g_rn[MAXN * HEADS];   // per-head reciprocal norms [N,4]
static __device__ float g_acc[MAXN * HID];    // aggregated messages [N,64]
static __device__ int   g_cnt[MAXN];          // in-degree per node
static __device__ int   g_start[MAXN];        // bin start offsets
static __device__ int   g_fill[MAXN];         // scatter cursors
static __device__ int   g_elist[MAXE];        // binned source (col) indices
static __device__ int   g_total;              // global bin cursor
static __device__ int   g_is64;               // edge_index dtype flag

// ---------------------------------------------------------------------------
// Detect edge_index dtype, reset bin cursor, zero g_cnt (all on stream B so
// the binning chain never depends on the GEMM stream).
// ---------------------------------------------------------------------------
__global__ void __launch_bounds__(256) detect_zero_kernel(
    const int* __restrict__ ei, int N)
{
    int idx = blockIdx.x * 256 + threadIdx.x;
    if (idx < N) g_cnt[idx] = 0;
    if (idx == 0) {
        int cnt = 0;
        for (int i = 0; i < 64; i++) {
            if (ei[2 * i + 1] != 0) cnt++;
        }
        g_is64 = (cnt == 0) ? 1 : 0;
        g_total = 0;
    }
}

// ---------------------------------------------------------------------------
// Kernel 1: h = x @ lin_w^T  (N x 128 @ 128 x 64), fused per-head rnorm +
// fp16 h write. 256-node x 64-out tile, 8x8 register tile (LDS-balanced).
// ---------------------------------------------------------------------------
__global__ void __launch_bounds__(256) gemm_norm_kernel(
    const float* __restrict__ x, const float* __restrict__ w, int N)
{
    __shared__ float xs[32][260];  // xs[k][m], m = node within 256-tile
    __shared__ float ws[32][68];   // ws[k][j]

    const int tid = threadIdx.x;
    const int tx = tid & 7;        // output group (8 outputs)
    const int ty = tid >> 3;       // node group (8 nodes), 0..31
    const int nb = blockIdx.x * 256;

    float acc[8][8];
#pragma unroll
    for (int a = 0; a < 8; a++)
#pragma unroll
        for (int b = 0; b < 8; b++) acc[a][b] = 0.f;

    for (int kc = 0; kc < IN_CH; kc += 32) {
        // Stage x tile: 256 nodes x 32 k (2048 float4, 8 per thread)
#pragma unroll
        for (int r = 0; r < 8; r++) {
            int idx = tid + 256 * r;
            int m = idx & 255, k4 = idx >> 8;
            float4 v = make_float4(0.f, 0.f, 0.f, 0.f);
            int node = nb + m;
            if (node < N)
                v = *reinterpret_cast<const float4*>(&x[node * IN_CH + kc + k4 * 4]);
            xs[k4 * 4 + 0][m] = v.x; xs[k4 * 4 + 1][m] = v.y;
            xs[k4 * 4 + 2][m] = v.z; xs[k4 * 4 + 3][m] = v.w;
        }
        // Stage w tile: 64 j x 32 k (512 float4, 2 per thread)
#pragma unroll
        for (int r = 0; r < 2; r++) {
            int idx = tid + 256 * r;
            int j = idx & 63, k4 = idx >> 6;
            float4 v = *reinterpret_cast<const float4*>(&w[j * IN_CH + kc + k4 * 4]);
            ws[k4 * 4 + 0][j] = v.x; ws[k4 * 4 + 1][j] = v.y;
            ws[k4 * 4 + 2][j] = v.z; ws[k4 * 4 + 3][j] = v.w;
        }
        __syncthreads();

#pragma unroll
        for (int k = 0; k < 32; k++) {
            float4 xv0 = *reinterpret_cast<float4*>(&xs[k][ty * 8]);
            float4 xv1 = *reinterpret_cast<float4*>(&xs[k][ty * 8 + 4]);
            float4 wv0 = *reinterpret_cast<float4*>(&ws[k][tx * 8]);
            float4 wv1 = *reinterpret_cast<float4*>(&ws[k][tx * 8 + 4]);
            float xr[8] = {xv0.x, xv0.y, xv0.z, xv0.w, xv1.x, xv1.y, xv1.z, xv1.w};
            float wr[8] = {wv0.x, wv0.y, wv0.z, wv0.w, wv1.x, wv1.y, wv1.z, wv1.w};
#pragma unroll
            for (int a = 0; a < 8; a++)
#pragma unroll
                for (int b = 0; b < 8; b++) acc[a][b] += xr[a] * wr[b];
        }
        __syncthreads();
    }

    // Epilogue: thread owns outputs tx*8..tx*8+7 (half of head tx>>1) for
    // 8 nodes. Pair (tid, tid^1) covers one full head.
#pragma unroll
    for (int mi = 0; mi < 8; mi++) {
        int node = nb + ty * 8 + mi;
        float s = 0.f;
#pragma unroll
        for (int b = 0; b < 8; b++) s += acc[mi][b] * acc[mi][b];
        s += __shfl_xor_sync(0xffffffffu, s, 1);
        if (node < N) {
            union { __half2 h[4]; uint4 u; } pk;
#pragma unroll
            for (int b = 0; b < 4; b++)
                pk.h[b] = __floats2half2_rn(acc[mi][2 * b], acc[mi][2 * b + 1]);
            g_h2[node * 8 + tx] = pk.u;
            if ((tx & 1) == 0) {
                g_rn[node * HEADS + (tx >> 1)] = 1.0f / fmaxf(sqrtf(s), 1e-12f);
            }
        }
    }
}

// ---------------------------------------------------------------------------
// Kernel 2a: in-degree histogram.
// ---------------------------------------------------------------------------
__global__ void __launch_bounds__(256) hist_kernel(
    const long long* __restrict__ ei, int E)
{
    int e = blockIdx.x * 256 + threadIdx.x;
    if (e >= E) return;
    int row = g_is64 ? (int)ei[e] : reinterpret_cast<const int*>(ei)[e];
    atomicAdd(&g_cnt[row], 1);
}

// ---------------------------------------------------------------------------
// Kernel 2b: bin offset assignment (warp scan + one global cursor atomic).
// ---------------------------------------------------------------------------
__global__ void __launch_bounds__(256) offsets_kernel(int N)
{
    const int idx = blockIdx.x * 256 + threadIdx.x;
    const int lane = threadIdx.x & 31;
    const int cnt = (idx < N) ? g_cnt[idx] : 0;

    int incl = cnt;
#pragma unroll
    for (int off = 1; off < 32; off <<= 1) {
        int v = __shfl_up_sync(0xffffffffu, incl, off);
        if (lane >= off) incl += v;
    }
    int base = 0;
    if (lane == 31) base = atomicAdd(&g_total, incl);
    base = __shfl_sync(0xffffffffu, base, 31);

    if (idx < N) {
        int s = base + incl - cnt;
        g_start[idx] = s;
        g_fill[idx] = s;
    }
}

// ---------------------------------------------------------------------------
// Kernel 2c: scatter source (col) indices into per-row bins.
// ---------------------------------------------------------------------------
__global__ void __launch_bounds__(256) scatter_kernel(
    const long long* __restrict__ ei, int E)
{
    int e = blockIdx.x * 256 + threadIdx.x;
    if (e >= E) return;
    int row, col;
    if (g_is64) {
        row = (int)ei[e];
        col = (int)ei[E + e];
    } else {
        const int* p = reinterpret_cast<const int*>(ei);
        row = p[e];
        col = p[E + e];
    }
    int pos = atomicAdd(&g_fill[row], 1);
    g_elist[pos] = col;
}

// ---------------------------------------------------------------------------
// Kernel 2d: atomic-free aggregation. One warp per target node.
// 8 edge groups x 4 head slices; head dot is lane-local (no shuffles inside
// the divergent loop); cross-group reduction after the loop.
// ---------------------------------------------------------------------------
__global__ void __launch_bounds__(256) accum_kernel(int N)
{
    const int warp = (blockIdx.x * 256 + threadIdx.x) >> 5;
    const int lane = threadIdx.x & 31;
    if (warp >= N) return;
    const int n = warp;
    const int g = lane >> 2;     // edge group 0..7
    const int t = lane & 3;      // head index 0..3

    uint4 rv0 = g_h2[n * 8 + 2 * t];
    uint4 rv1 = g_h2[n * 8 + 2 * t + 1];
    float2 r[8];
    {
        const __half2* rh0 = reinterpret_cast<const __half2*>(&rv0);
        const __half2* rh1 = reinterpret_cast<const __half2*>(&rv1);
#pragma unroll
        for (int i = 0; i < 4; i++) { r[i] = __half22float2(rh0[i]); r[i + 4] = __half22float2(rh1[i]); }
    }
    const float rnr = g_rn[n * HEADS + t];

    const int start = g_start[n];
    const int cnt = g_cnt[n];

    float acc[16];
#pragma unroll
    for (int i = 0; i < 16; i++) acc[i] = 0.f;

    for (int i = g; i < cnt; i += 8) {
        int col = g_elist[start + i];
        uint4 cv0 = g_h2[col * 8 + 2 * t];
        uint4 cv1 = g_h2[col * 8 + 2 * t + 1];
        const __half2* ch0 = reinterpret_cast<const __half2*>(&cv0);
        const __half2* ch1 = reinterpret_cast<const __half2*>(&cv1);
        float2 c[8];
#pragma unroll
        for (int j = 0; j < 4; j++) { c[j] = __half22float2(ch0[j]); c[j + 4] = __half22float2(ch1[j]); }

        float d = 0.f;
#pragma unroll
        for (int j = 0; j < 8; j++) d += c[j].x * r[j].x + c[j].y * r[j].y;

        float cosv = d * g_rn[col * HEADS + t] * rnr;
        cosv = fminf(fmaxf(cosv, 1e-6f), 1.0f);    // clip; B_EXP=2 => scale=cos

#pragma unroll
        for (int j = 0; j < 8; j++) {
            acc[2 * j + 0] += c[j].x * cosv;
            acc[2 * j + 1] += c[j].y * cosv;
        }
    }

#pragma unroll
    for (int j = 0; j < 16; j++) {
        acc[j] += __shfl_xor_sync(0xffffffffu, acc[j], 4);
        acc[j] += __shfl_xor_sync(0xffffffffu, acc[j], 8);
        acc[j] += __shfl_xor_sync(0xffffffffu, acc[j], 16);
    }

    if (g == 0) {
        float* p = &g_acc[n * HID + t * 16];
        *reinterpret_cast<float4*>(p +  0) = make_float4(acc[0],  acc[1],  acc[2],  acc[3]);
        *reinterpret_cast<float4*>(p +  4) = make_float4(acc[4],  acc[5],  acc[6],  acc[7]);
        *reinterpret_cast<float4*>(p +  8) = make_float4(acc[8],  acc[9],  acc[10], acc[11]);
        *reinterpret_cast<float4*>(p + 12) = make_float4(acc[12], acc[13], acc[14], acc[15]);
    }
}

// ---------------------------------------------------------------------------
// Kernel 3: BcosLinearNoBias (64x64 GEMM) + LayerNorm, persistent blocks.
// ---------------------------------------------------------------------------
__global__ void __launch_bounds__(256) final_kernel(
    const float* __restrict__ bw, const float* __restrict__ gamma,
    const float* __restrict__ beta, float* __restrict__ out, int N)
{
    __shared__ float as[64][68];    // as[k][m]   acc tile (transposed)
    __shared__ float ws[64][68];    // ws[k][j]   bw tile (transposed)
    __shared__ float psum[4][64];   // per-quarter partial row sumsq
    __shared__ float orn_s[64];     // 1/||acc_row||
    __shared__ float wrn_s[64];     // 1/||bw_j||

    const int tid = threadIdx.x;
    const int tx = tid & 15;
    const int ty = tid >> 4;

    {
        const int j = tid & 63;
        const int q = tid >> 6;
#pragma unroll
        for (int rr = 0; rr < 4; rr++) {
            int k4 = q + 4 * rr;
            float4 v = *reinterpret_cast<const float4*>(&bw[j * HID + k4 * 4]);
            ws[k4 * 4 + 0][j] = v.x; ws[k4 * 4 + 1][j] = v.y;
            ws[k4 * 4 + 2][j] = v.z; ws[k4 * 4 + 3][j] = v.w;
        }
    }
    __syncthreads();
    if (tid < 64) {
        float s = 0.f;
#pragma unroll
        for (int k = 0; k < 64; k++) { float v = ws[k][tid]; s += v * v; }
        wrn_s[tid] = 1.0f / fmaxf(sqrtf(s), 1e-12f);
    }
    __syncthreads();

    const float w0 = wrn_s[tx * 4 + 0], w1 = wrn_s[tx * 4 + 1];
    const float w2 = wrn_s[tx * 4 + 2], w3 = wrn_s[tx * 4 + 3];
    const float4 gm = *reinterpret_cast<const float4*>(&gamma[tx * 4]);
    const float4 bt = *reinterpret_cast<const float4*>(&beta[tx * 4]);

    const int ntiles = (N + 63) >> 6;
    for (int tile = blockIdx.x; tile < ntiles; tile += gridDim.x) {
        const int nb = tile * 64;

        {
            const int m = tid & 63;
            const int q = tid >> 6;
            const int node = nb + m;
            float ss = 0.f;
#pragma unroll
            for (int rr = 0; rr < 4; rr++) {
                int k4 = q + 4 * rr;
                float4 v = make_float4(0.f, 0.f, 0.f, 0.f);
                if (node < N)
                    v = *reinterpret_cast<const float4*>(&g_acc[node * HID + k4 * 4]);
                as[k4 * 4 + 0][m] = v.x; as[k4 * 4 + 1][m] = v.y;
                as[k4 * 4 + 2][m] = v.z; as[k4 * 4 + 3][m] = v.w;
                ss += v.x * v.x + v.y * v.y + v.z * v.z + v.w * v.w;
            }
            psum[q][m] = ss;
        }
        __syncthreads();

        if (tid < 64) {
            float s = psum[0][tid] + psum[1][tid] + psum[2][tid] + psum[3][tid];
            orn_s[tid] = 1.0f / fmaxf(sqrtf(s), 1e-12f);
        }

        float acc[4][4];
#pragma unroll
        for (int a = 0; a < 4; a++)
#pragma unroll
            for (int b = 0; b < 4; b++) acc[a][b] = 0.f;

#pragma unroll
        for (int k = 0; k < 64; k++) {
            float4 xv = *reinterpret_cast<float4*>(&as[k][ty * 4]);
            float4 wv = *reinterpret_cast<float4*>(&ws[k][tx * 4]);
            float xr[4] = {xv.x, xv.y, xv.z, xv.w};
            float wr[4] = {wv.x, wv.y, wv.z, wv.w};
#pragma unroll
            for (int a = 0; a < 4; a++)
#pragma unroll
                for (int b = 0; b < 4; b++) acc[a][b] += xr[a] * wr[b];
        }
        __syncthreads();

#pragma unroll
        for (int mi = 0; mi < 4; mi++) {
            const int node = nb + ty * 4 + mi;
            const float orn = orn_s[ty * 4 + mi];

            float l0 = acc[mi][0], l1 = acc[mi][1], l2 = acc[mi][2], l3 = acc[mi][3];
            float y0 = l0 * fminf(fmaxf(l0 * orn * w0, 1e-6f), 1.0f);
            float y1 = l1 * fminf(fmaxf(l1 * orn * w1, 1e-6f), 1.0f);
            float y2 = l2 * fminf(fmaxf(l2 * orn * w2, 1e-6f), 1.0f);
            float y3 = l3 * fminf(fmaxf(l3 * orn * w3, 1e-6f), 1.0f);

            float sum = y0 + y1 + y2 + y3;
#pragma unroll
            for (int o = 8; o > 0; o >>= 1) sum += __shfl_xor_sync(0xffffffffu, sum, o);
            float mu = sum * (1.0f / 64.0f);

            float d0 = y0 - mu, d1 = y1 - mu, d2 = y2 - mu, d3 = y3 - mu;
            float vs = d0 * d0 + d1 * d1 + d2 * d2 + d3 * d3;
#pragma unroll
            for (int o = 8; o > 0; o >>= 1) vs += __shfl_xor_sync(0xffffffffu, vs, o);
            float inv = rsqrtf(vs * (1.0f / 64.0f) + 1e-5f);

            if (node < N) {
                float4 ov = make_float4(d0 * inv * gm.x + bt.x,
                                        d1 * inv * gm.y + bt.y,
                                        d2 * inv * gm.z + bt.z,
                                        d3 * inv * gm.w + bt.w);
                *reinterpret_cast<float4*>(&out[node * HID + tx * 4]) = ov;
            }
        }
        __syncthreads();
    }
}

// ---------------------------------------------------------------------------
extern "C" void kernel_launch(void* const* d_in, const int* in_sizes, int n_in,
                              void* d_out, int out_size)
{
    const float*     x     = (const float*)d_in[0];
    const long long* ei    = (const long long*)d_in[1];
    const float*     lin_w = (const float*)d_in[2];
    const float*     bw    = (const float*)d_in[3];
    const float*     gamma = (const float*)d_in[4];
    const float*     beta  = (const float*)d_in[5];

    const int N = in_sizes[0] / IN_CH;
    const int E = in_sizes[1] / 2;

    // Lazy one-time stream/event creation (happens on the correctness run,
    // before graph capture; no device memory involved).
    static cudaStream_t s_b = nullptr;
    static cudaEvent_t ev_fork = nullptr, ev_join = nullptr;
    if (s_b == nullptr) {
        cudaStreamCreate(&s_b);
        cudaEventCreateWithFlags(&ev_fork, cudaEventDisableTiming);
        cudaEventCreateWithFlags(&ev_join, cudaEventDisableTiming);
    }

    // Fork: binning chain on stream B, GEMM on the main stream.
    cudaEventRecord(ev_fork, 0);
    cudaStreamWaitEvent(s_b, ev_fork, 0);

    detect_zero_kernel<<<(N + 255) / 256, 256, 0, s_b>>>((const int*)ei, N);
    hist_kernel<<<(E + 255) / 256, 256, 0, s_b>>>(ei, E);
    offsets_kernel<<<(N + 255) / 256, 256, 0, s_b>>>(N);
    scatter_kernel<<<(E + 255) / 256, 256, 0, s_b>>>(ei, E);
    cudaEventRecord(ev_join, s_b);

    gemm_norm_kernel<<<(N + 255) / 256, 256>>>(x, lin_w, N);

    // Join: accum needs both h2/rn (main) and elist (B).
    cudaStreamWaitEvent(0, ev_join, 0);
    accum_kernel<<<(N + 7) / 8, 256>>>(N);
    final_kernel<<<296, 256>>>(bw, gamma, beta, (float*)d_out, N);
}